// round 7
// baseline (speedup 1.0000x reference)
#include <cuda_runtime.h>
#include <math.h>

// x[B=32, C=1, F=128, T=4096] fp32 -> out[B, C, T, F] fp32 (PCEN).
#define NB 32
#define NF 128
#define NT 4096
#define EPSF 1e-5f
#define HALF 2048
#define NIT 8             // iterations per half: 8 x 256 t

__device__ __forceinline__ float flg2(float v) {
    float r; asm("lg2.approx.f32 %0, %1;" : "=f"(r) : "f"(v)); return r;
}
__device__ __forceinline__ float fex2(float v) {
    float r; asm("ex2.approx.f32 %0, %1;" : "=f"(r) : "f"(v)); return r;
}

// Block = 512 threads = 16 warps = 16 f-rows x ONE time-half (grid T-split).
// Register-diet version: the warp scan consumes only the lane's zero-carry
// segment END (l7); after the scan delivers Min, m_k is regenerated with the
// plain serial EMA (m_k = c*m_{k-1} + s*x_k) — same FMA count, ~13 fewer
// live registers, enabling 4 blocks/SM (single wave: 592 slots >= 512 blocks).
__global__ __launch_bounds__(512, 4)
void pcen_kernel(const float* __restrict__ x,
                 const float* __restrict__ alpha,
                 const float* __restrict__ delta,
                 const float* __restrict__ rparam,
                 float* __restrict__ out)
{
    __shared__ float4 tile4[2][2][32][17];   // [buf][hh][tseg][f] 34.8KB

    const int tid  = threadIdx.x;
    const int wid  = tid >> 5;
    const int lane = tid & 31;
    const int h    = blockIdx.x & 1;            // time half
    const int fgi  = (blockIdx.x >> 1) & 7;
    const int b    = blockIdx.x >> 4;
    const int fg   = fgi << 4;
    const int f    = fg + wid;

    // s from t_val = 256
    const double sD = (sqrt(1.0 + 4.0 * 65536.0) - 1.0) / (2.0 * 65536.0);
    const float s = (float)sD;
    const float c = 1.0f - s;

    const double lc = log((double)c);
    const float c8pow   = (float)exp(lc * 8.0 * (double)lane);    // c^(8*lane)
    const float c8inv   = (float)exp(-lc * 8.0 * (double)lane);   // c^(-8*lane)
    const float c8powm1 = (float)exp(lc * 8.0 * (double)(lane - 1));
    const float c8pow1  = c8pow * (float)exp(lc * 8.0);           // c^(8*(lane+1))

    // Per-f parameters (uniform per warp)
    const float a   = expf(alpha[f]);
    const float d   = expf(delta[f]);
    const float rr  = expf(rparam[f]);
    const float drr = fex2(rr * flg2(d));
    const float na  = -a;

    const long row = ((long)(b * NF + f)) * NT;
    const float4* xr4 = (const float4*)(x + row);
    const float x0 = __ldg(&x[row]);

    float carry;
    if (h == 0) {
        carry = x0;   // m_{-1} = x_0 => m_0 = x_0 exactly
    } else {
        // pass A: exact EMA state at t=2047, scan-free & coalesced
        const float cinv256 = (float)exp(-lc * 256.0);
        float A = 0.0f, w = 1.0f;
        #pragma unroll
        for (int i = 0; i < NIT; ++i) {
            float4 a0 = __ldg(&xr4[i * 64 + 2 * lane]);
            float4 a1 = __ldg(&xr4[i * 64 + 2 * lane + 1]);
            float l = s * a0.x;
            l = fmaf(c, l, s * a0.y); l = fmaf(c, l, s * a0.z);
            l = fmaf(c, l, s * a0.w); l = fmaf(c, l, s * a1.x);
            l = fmaf(c, l, s * a1.y); l = fmaf(c, l, s * a1.z);
            l = fmaf(c, l, s * a1.w);
            A = fmaf(l, w, A);
            w *= cinv256;
        }
        float v = A * c8inv;
        #pragma unroll
        for (int off = 16; off >= 1; off >>= 1)
            v += __shfl_xor_sync(0xffffffffu, v, off);
        carry = fmaf((float)exp(lc * 2048.0), x0,
                     v * (float)exp(lc * 2040.0));   // m_2047
    }

    const int base4 = h * (HALF / 4);
    float4 xv0 = __ldg(&xr4[base4 + 2 * lane]);
    float4 xv1 = __ldg(&xr4[base4 + 2 * lane + 1]);

    const int fl   = tid & 15;          // read-phase mapping
    const int tseg = tid >> 4;

    int buf = 0;
    for (int it = 0; it < NIT; ++it, buf ^= 1) {
        // --- zero-carry segment end l7 (only value the scan needs) ---
        float l = s * xv0.x;
        l = fmaf(c, l, s * xv0.y); l = fmaf(c, l, s * xv0.z);
        l = fmaf(c, l, s * xv0.w); l = fmaf(c, l, s * xv1.x);
        l = fmaf(c, l, s * xv1.y); l = fmaf(c, l, s * xv1.z);
        l = fmaf(c, l, s * xv1.w);

        // --- warp scan of segment totals (rescaled by c^-8j) ---
        float u = l * c8inv;
        #pragma unroll
        for (int off = 1; off < 32; off <<= 1) {
            float n = __shfl_up_sync(0xffffffffu, u, off);
            if (lane >= off) u += n;
        }
        float uprev = __shfl_up_sync(0xffffffffu, u, 1);
        float Min = (lane == 0) ? carry
                                : fmaf(c8powm1, uprev, c8pow * carry);
        carry = __shfl_sync(0xffffffffu,
                            fmaf(c8pow, u, c8pow1 * carry), 31);

        // --- serial EMA regen + pointwise, 4 at a time (low reg pressure) ---
        float m = Min;
        m = fmaf(c, m, s * xv0.x);
        float p0 = fex2(rr * flg2(fmaf(xv0.x, fex2(na * flg2(m + EPSF)), d))) - drr;
        m = fmaf(c, m, s * xv0.y);
        float p1 = fex2(rr * flg2(fmaf(xv0.y, fex2(na * flg2(m + EPSF)), d))) - drr;
        m = fmaf(c, m, s * xv0.z);
        float p2 = fex2(rr * flg2(fmaf(xv0.z, fex2(na * flg2(m + EPSF)), d))) - drr;
        m = fmaf(c, m, s * xv0.w);
        float p3 = fex2(rr * flg2(fmaf(xv0.w, fex2(na * flg2(m + EPSF)), d))) - drr;
        tile4[buf][0][lane][wid] = make_float4(p0, p1, p2, p3);

        m = fmaf(c, m, s * xv1.x);
        p0 = fex2(rr * flg2(fmaf(xv1.x, fex2(na * flg2(m + EPSF)), d))) - drr;
        m = fmaf(c, m, s * xv1.y);
        p1 = fex2(rr * flg2(fmaf(xv1.y, fex2(na * flg2(m + EPSF)), d))) - drr;
        m = fmaf(c, m, s * xv1.z);
        p2 = fex2(rr * flg2(fmaf(xv1.z, fex2(na * flg2(m + EPSF)), d))) - drr;
        m = fmaf(c, m, s * xv1.w);
        p3 = fex2(rr * flg2(fmaf(xv1.w, fex2(na * flg2(m + EPSF)), d))) - drr;
        tile4[buf][1][lane][wid] = make_float4(p0, p1, p2, p3);

        // branch-free prefetch (wraps to chunk 0 on last iter)
        int nb4 = base4 + ((it + 1) & 7) * 64;
        xv0 = __ldg(&xr4[nb4 + 2 * lane]);
        xv1 = __ldg(&xr4[nb4 + 2 * lane + 1]);

        __syncthreads();

        // read transposed (2x LDS.128, conflict-free), 8x coalesced STG.32
        float4 v0 = tile4[buf][0][tseg][fl];
        float4 v1 = tile4[buf][1][tseg][fl];
        float* op = &out[((long)b * NT + (long)h * HALF + it * 256 + tseg * 8) * NF
                         + fg + fl];
        op[0]      = v0.x;
        op[NF]     = v0.y;
        op[2 * NF] = v0.z;
        op[3 * NF] = v0.w;
        op[4 * NF] = v1.x;
        op[5 * NF] = v1.y;
        op[6 * NF] = v1.z;
        op[7 * NF] = v1.w;
    }
}

extern "C" void kernel_launch(void* const* d_in, const int* in_sizes, int n_in,
                              void* d_out, int out_size) {
    (void)in_sizes; (void)n_in; (void)out_size;
    const float* x     = (const float*)d_in[0];
    const float* alpha = (const float*)d_in[1];
    const float* delta = (const float*)d_in[2];
    const float* rpar  = (const float*)d_in[3];
    float* out = (float*)d_out;

    // 512 blocks = 32 b x 8 f-groups(16) x 2 time-halves; 512 threads.
    pcen_kernel<<<NB * (NF / 16) * 2, 512>>>(x, alpha, delta, rpar, out);
}

// round 8
// speedup vs baseline: 1.1044x; 1.1044x over previous
#include <cuda_runtime.h>
#include <math.h>

// x[B=32, C=1, F=128, T=4096] fp32 -> out[B, C, T, F] fp32 (PCEN).
#define NB 32
#define NF 128
#define NT 4096
#define EPSF 1e-5f
#define HALF 2048
#define NIT 8             // iterations per half: 8 x 256 t

__device__ __forceinline__ float flg2(float v) {
    float r; asm("lg2.approx.f32 %0, %1;" : "=f"(r) : "f"(v)); return r;
}
__device__ __forceinline__ float fex2(float v) {
    float r; asm("ex2.approx.f32 %0, %1;" : "=f"(r) : "f"(v)); return r;
}

// Block = 512 threads = 16 warps = 16 f-rows x ONE time-half (grid T-split).
// Instruction-diet version of the R6 structure:
//  - EMA carried in x-units (M = m/s): the zero-carry L-chain is pure FFMA.
//  - e_k = m_k + eps folded into the recombine FFMAs.
//  - exclusive scan via (u - u0) instead of an extra shfl + lane-0 select.
//  - loop-carried pointers; STG offsets as immediates.
__global__ __launch_bounds__(512, 3)
void pcen_kernel(const float* __restrict__ x,
                 const float* __restrict__ alpha,
                 const float* __restrict__ delta,
                 const float* __restrict__ rparam,
                 float* __restrict__ out)
{
    __shared__ float4 tile4[2][2][32][17];   // [buf][hh][tseg][f] 34.8KB

    const int tid  = threadIdx.x;
    const int wid  = tid >> 5;
    const int lane = tid & 31;
    const int h    = blockIdx.x & 1;            // time half
    const int fgi  = (blockIdx.x >> 1) & 7;
    const int b    = blockIdx.x >> 4;
    const int fg   = fgi << 4;
    const int f    = fg + wid;

    // s from t_val = 256
    const double sD = (sqrt(1.0 + 4.0 * 65536.0) - 1.0) / (2.0 * 65536.0);
    const float s  = (float)sD;
    const float rs = (float)(1.0 / sD);
    const float c  = 1.0f - s;
    const float c2 = c * c,  c3 = c2 * c,  c4 = c2 * c2;
    const float c5 = c4 * c, c6 = c4 * c2, c7 = c4 * c3, c8 = c4 * c4;

    const double lc = log((double)c);
    const float c8pow   = (float)exp(lc * 8.0 * (double)lane);    // c^(8*lane)
    const float c8inv   = (float)exp(-lc * 8.0 * (double)lane);   // c^(-8*lane)
    const float c8powm1 = (float)exp(lc * 8.0 * (double)(lane - 1));
    const float c8pow1  = c8pow * c8;                             // c^(8*(lane+1))

    // Per-f parameters (uniform per warp)
    const float a   = expf(alpha[f]);
    const float d   = expf(delta[f]);
    const float rr  = expf(rparam[f]);
    const float drr = fex2(rr * flg2(d));
    const float na  = -a;

    const long row = ((long)(b * NF + f)) * NT;
    const float4* xr4 = (const float4*)(x + row);
    const float x0 = __ldg(&x[row]);

    // Carry in M-units (m = s*M).  M_{-1} = x0/s  =>  m_0 = x0 (to rounding).
    float carryM;
    if (h == 0) {
        carryM = x0 * rs;
    } else {
        // pass A: exact M state at t=2047, scan-free & coalesced (x-units)
        const float cinv256 = (float)exp(-lc * 256.0);
        float A = 0.0f, w = 1.0f;
        #pragma unroll
        for (int i = 0; i < NIT; ++i) {
            float4 a0 = __ldg(&xr4[i * 64 + 2 * lane]);
            float4 a1 = __ldg(&xr4[i * 64 + 2 * lane + 1]);
            float L = a0.x;
            L = fmaf(c, L, a0.y); L = fmaf(c, L, a0.z);
            L = fmaf(c, L, a0.w); L = fmaf(c, L, a1.x);
            L = fmaf(c, L, a1.y); L = fmaf(c, L, a1.z);
            L = fmaf(c, L, a1.w);
            A = fmaf(L, w, A);
            w *= cinv256;
        }
        float v = A * c8inv;
        #pragma unroll
        for (int off = 16; off >= 1; off >>= 1)
            v += __shfl_xor_sync(0xffffffffu, v, off);
        carryM = fmaf((float)exp(lc * 2048.0), x0 * rs,
                      v * (float)exp(lc * 2040.0));   // M_2047
    }

    const int base4 = h * (HALF / 4);
    const float4* xpre = xr4 + base4 + 2 * lane;   // this lane's float4 pair base
    float4 xv0 = __ldg(&xpre[0]);
    float4 xv1 = __ldg(&xpre[1]);

    const int fl   = tid & 15;          // read-phase mapping
    const int tseg = tid >> 4;

    // loop-carried output pointer: (b, t = h*HALF + tseg*8, f = fg+fl)
    float* op = &out[((long)b * NT + (long)h * HALF + tseg * 8) * NF + fg + fl];

    int buf = 0;
    for (int it = 0; it < NIT; ++it, buf ^= 1) {
        // --- zero-carry L-chain in x-units (pure FFMA) ---
        float L0 = xv0.x;
        float L1 = fmaf(c, L0, xv0.y);
        float L2 = fmaf(c, L1, xv0.z);
        float L3 = fmaf(c, L2, xv0.w);
        float L4 = fmaf(c, L3, xv1.x);
        float L5 = fmaf(c, L4, xv1.y);
        float L6 = fmaf(c, L5, xv1.z);
        float L7 = fmaf(c, L6, xv1.w);

        // --- warp scan of rescaled segment totals ---
        float u0 = L7 * c8inv;
        float u  = u0;
        #pragma unroll
        for (int off = 1; off < 32; off <<= 1) {
            float n = __shfl_up_sync(0xffffffffu, u, off);
            if (lane >= off) u += n;
        }
        float uex  = u - u0;                           // exact 0 on lane 0
        float MinM = fmaf(c8powm1, uex, c8pow * carryM);
        carryM = __shfl_sync(0xffffffffu,
                             fmaf(c8pow, u, c8pow1 * carryM), 31);

        // --- recombine with eps folded in:  e_k = s*L_k + c^{k+1}*s*MinM + eps
        float B = s * MinM;
        float e0 = fmaf(c,  B, fmaf(s, L0, EPSF));
        float e1 = fmaf(c2, B, fmaf(s, L1, EPSF));
        float e2 = fmaf(c3, B, fmaf(s, L2, EPSF));
        float e3 = fmaf(c4, B, fmaf(s, L3, EPSF));

        float p0 = fex2(rr * flg2(fmaf(xv0.x, fex2(na * flg2(e0)), d))) - drr;
        float p1 = fex2(rr * flg2(fmaf(xv0.y, fex2(na * flg2(e1)), d))) - drr;
        float p2 = fex2(rr * flg2(fmaf(xv0.z, fex2(na * flg2(e2)), d))) - drr;
        float p3 = fex2(rr * flg2(fmaf(xv0.w, fex2(na * flg2(e3)), d))) - drr;
        tile4[buf][0][lane][wid] = make_float4(p0, p1, p2, p3);

        float e4 = fmaf(c5, B, fmaf(s, L4, EPSF));
        float e5 = fmaf(c6, B, fmaf(s, L5, EPSF));
        float e6 = fmaf(c7, B, fmaf(s, L6, EPSF));
        float e7 = fmaf(c8, B, fmaf(s, L7, EPSF));

        p0 = fex2(rr * flg2(fmaf(xv1.x, fex2(na * flg2(e4)), d))) - drr;
        p1 = fex2(rr * flg2(fmaf(xv1.y, fex2(na * flg2(e5)), d))) - drr;
        p2 = fex2(rr * flg2(fmaf(xv1.z, fex2(na * flg2(e6)), d))) - drr;
        p3 = fex2(rr * flg2(fmaf(xv1.w, fex2(na * flg2(e7)), d))) - drr;
        tile4[buf][1][lane][wid] = make_float4(p0, p1, p2, p3);

        // branch-free prefetch (wraps to chunk 0 on last iter)
        int nb = ((it + 1) & 7) << 6;
        xv0 = __ldg(&xpre[nb]);
        xv1 = __ldg(&xpre[nb + 1]);

        __syncthreads();

        // read transposed (2x LDS.128, conflict-free), 8x coalesced STG.32
        float4 v0 = tile4[buf][0][tseg][fl];
        float4 v1 = tile4[buf][1][tseg][fl];
        op[0]      = v0.x;
        op[NF]     = v0.y;
        op[2 * NF] = v0.z;
        op[3 * NF] = v0.w;
        op[4 * NF] = v1.x;
        op[5 * NF] = v1.y;
        op[6 * NF] = v1.z;
        op[7 * NF] = v1.w;
        op += 256 * NF;
    }
}

extern "C" void kernel_launch(void* const* d_in, const int* in_sizes, int n_in,
                              void* d_out, int out_size) {
    (void)in_sizes; (void)n_in; (void)out_size;
    const float* x     = (const float*)d_in[0];
    const float* alpha = (const float*)d_in[1];
    const float* delta = (const float*)d_in[2];
    const float* rpar  = (const float*)d_in[3];
    float* out = (float*)d_out;

    // 512 blocks = 32 b x 8 f-groups(16) x 2 time-halves; 512 threads.
    pcen_kernel<<<NB * (NF / 16) * 2, 512>>>(x, alpha, delta, rpar, out);
}